// round 6
// baseline (speedup 1.0000x reference)
#include <cuda_runtime.h>
#include <math_constants.h>

#define THREADS 256
#define NBLK 512              // must all be co-resident (148 SMs x 4)
#define SEG 32768             // elements per segment (one per block at n=2^24)
#define MAXSEG 4096
#define NELEM_MAX (1 << 24)

// ---------------- device scratch (no allocations allowed) ----------------
__device__ unsigned int d_umin = 0xFFFFFFFFu;   // re-armed each run
__device__ unsigned int d_umax = 0u;
__device__ int d_hist[256];                     // zeroed each run after use
__device__ int d_bhT[256][MAXSEG];              // bin-major per-seg histogram
__device__ unsigned char d_qbuf[NELEM_MAX];
__device__ volatile unsigned int g_cnt = 0;     // grid barrier state
__device__ volatile unsigned int g_gen = 0;

// order-preserving float <-> uint mapping for atomic min/max
__device__ __forceinline__ unsigned int enc_f(float f) {
    unsigned int u = __float_as_uint(f);
    return (u & 0x80000000u) ? ~u : (u | 0x80000000u);
}
__device__ __forceinline__ float dec_f(unsigned int e) {
    unsigned int u = (e & 0x80000000u) ? (e & 0x7FFFFFFFu) : ~e;
    return __uint_as_float(u);
}

// exact quantization matching jnp: ((x-min)/range)*255, round-half-even
__device__ __forceinline__ int quant(float v, float minv, float range) {
    float nn = __fdiv_rn(v - minv, range);      // IEEE divide (no fast-math)
    float ss = __fmul_rn(nn, 255.0f);           // IEEE multiply
    int q = (int)rintf(ss);                     // RNE, same as jnp.round
    return min(255, max(0, q));
}

// sense-reversing software grid barrier (all NBLK blocks co-resident)
__device__ __forceinline__ void grid_barrier() {
    __syncthreads();
    if (threadIdx.x == 0) {
        unsigned int my = g_gen;                // gen can't change until all arrive
        __threadfence();
        unsigned int prev = atomicAdd((unsigned int*)&g_cnt, 1u);
        if (prev == NBLK - 1) {
            g_cnt = 0;
            __threadfence();
            g_gen = my + 1;
        } else {
            while (g_gen == my) { __nanosleep(64); }
        }
        __threadfence();
    }
    __syncthreads();
}

__global__ void __launch_bounds__(THREADS, 4)
k_fused(const float* __restrict__ x, float* __restrict__ out,
        int n, int keep, int nseg, long long out_n) {
    __shared__ int sh[8][256];     // warp hists; aliased as scan buffer in ph3
    __shared__ float smn[8], smx[8];
    __shared__ int red[8], s_wtot[8];
    __shared__ int s_t, s_r, s_s;

    int tid = threadIdx.x;
    int lane = tid & 31, wid = tid >> 5;
    int b = blockIdx.x;

    // ================= phase 1: global min/max =================
    {
        float lmin = CUDART_INF_F, lmax = -CUDART_INF_F;
        for (int si = b; si < nseg; si += NBLK) {
            int segbase = si * SEG;
#pragma unroll 4
            for (int it = 0; it < SEG / 1024; it++) {
                int idx = segbase + it * 1024 + tid * 4;
                if (idx + 3 < n) {
                    float4 v = *reinterpret_cast<const float4*>(x + idx);
                    lmin = fminf(lmin, fminf(fminf(v.x, v.y), fminf(v.z, v.w)));
                    lmax = fmaxf(lmax, fmaxf(fmaxf(v.x, v.y), fmaxf(v.z, v.w)));
                } else {
                    for (int m = 0; m < 4; m++) {
                        int j = idx + m;
                        if (j < n) {
                            float v = x[j];
                            lmin = fminf(lmin, v);
                            lmax = fmaxf(lmax, v);
                        }
                    }
                }
            }
        }
#pragma unroll
        for (int o = 16; o; o >>= 1) {
            lmin = fminf(lmin, __shfl_xor_sync(0xFFFFFFFFu, lmin, o));
            lmax = fmaxf(lmax, __shfl_xor_sync(0xFFFFFFFFu, lmax, o));
        }
        if (lane == 0) { smn[wid] = lmin; smx[wid] = lmax; }
        __syncthreads();
        if (tid == 0) {
#pragma unroll
            for (int w = 1; w < 8; w++) {
                lmin = fminf(lmin, smn[w]);
                lmax = fmaxf(lmax, smx[w]);
            }
            atomicMin(&d_umin, enc_f(lmin));
            atomicMax(&d_umax, enc_f(lmax));
        }
    }
    grid_barrier();

    // ================= phase 2: quantize + histogram (x is L2-hot) =========
    float minv = dec_f(d_umin), maxv = dec_f(d_umax);
    float range = maxv - minv;
    if (range == 0.0f) range = 1.0f;

    for (int si = b; si < nseg; si += NBLK) {
        int segbase = si * SEG;
        for (int i = tid; i < 8 * 256; i += THREADS) ((int*)sh)[i] = 0;
        __syncthreads();
#pragma unroll 4
        for (int it = 0; it < SEG / 1024; it++) {
            int idx = segbase + it * 1024 + tid * 4;
            if (idx + 3 < n) {
                float4 v = *reinterpret_cast<const float4*>(x + idx);
                int q0 = quant(v.x, minv, range);
                int q1 = quant(v.y, minv, range);
                int q2 = quant(v.z, minv, range);
                int q3 = quant(v.w, minv, range);
                atomicAdd(&sh[wid][q0], 1);
                atomicAdd(&sh[wid][q1], 1);
                atomicAdd(&sh[wid][q2], 1);
                atomicAdd(&sh[wid][q3], 1);
                uchar4 qc;
                qc.x = (unsigned char)q0; qc.y = (unsigned char)q1;
                qc.z = (unsigned char)q2; qc.w = (unsigned char)q3;
                *reinterpret_cast<uchar4*>(d_qbuf + idx) = qc;
            } else {
                for (int m = 0; m < 4; m++) {
                    int j = idx + m;
                    if (j < n) {
                        int q = quant(x[j], minv, range);
                        atomicAdd(&sh[wid][q], 1);
                        d_qbuf[j] = (unsigned char)q;
                    }
                }
            }
        }
        __syncthreads();
        int tot = 0;
#pragma unroll
        for (int w = 0; w < 8; w++) tot += sh[w][tid];
        d_bhT[tid][si] = tot;
        atomicAdd(&d_hist[tid], tot);
        __syncthreads();
    }
    grid_barrier();

    // ================= phase 3: threshold (redundant per block) ============
    {
        int* sc = &sh[0][0];
        int h = d_hist[tid];
        sc[tid] = h;
        __syncthreads();
#pragma unroll
        for (int off = 1; off < 256; off <<= 1) {
            int add = (tid + off < 256) ? sc[tid + off] : 0;
            __syncthreads();
            sc[tid] += add;
            __syncthreads();
        }
        int ge = sc[tid];
        int gt = ge - h;
        if (gt < keep && ge >= keep) { s_t = tid; s_r = keep - gt; }
        __syncthreads();
    }
    int t = s_t, r = s_r;
    grid_barrier();                 // everyone has consumed d_hist / min-max
    if (b == 0) {                   // re-arm persistent state for next replay
        d_hist[tid] = 0;
        if (tid == 0) { d_umin = 0xFFFFFFFFu; d_umax = 0u; }
    }

    // ================= phase 4: sparsified output ==========================
    unsigned int ltmask = (1u << lane) - 1u;
    for (int si = b; si < nseg; si += NBLK) {
        int segbase = si * SEG;

        // s = #ties in segments before si (block reduction over d_bhT[t][:si])
        int part = 0;
        for (int j = tid; j < si; j += THREADS) part += d_bhT[t][j];
#pragma unroll
        for (int o = 16; o; o >>= 1) part += __shfl_xor_sync(0xFFFFFFFFu, part, o);
        if (lane == 0) red[wid] = part;
        __syncthreads();
        if (tid == 0) {
            int ssum = 0;
#pragma unroll
            for (int w = 0; w < 8; w++) ssum += red[w];
            s_s = ssum;
        }
        __syncthreads();
        int s = s_s;
        int e = s + d_bhT[t][si];

        int warpbase = segbase + wid * (SEG / 8);

        if (e <= r || s >= r) {
            // -------- fast path: pure streaming --------
            int keepv = (e <= r) ? t : (t + 1);
#pragma unroll 4
            for (int rr = 0; rr < SEG / 8 / 128; rr++) {
                int idx = warpbase + rr * 128 + lane * 4;
                if (idx + 3 < n) {
                    uchar4 q = *reinterpret_cast<const uchar4*>(d_qbuf + idx);
                    float4 ov;
                    ov.x = (q.x >= keepv) ? (float)q.x : 0.0f;
                    ov.y = (q.y >= keepv) ? (float)q.y : 0.0f;
                    ov.z = (q.z >= keepv) ? (float)q.z : 0.0f;
                    ov.w = (q.w >= keepv) ? (float)q.w : 0.0f;
                    *reinterpret_cast<float4*>(out + idx) = ov;
                } else {
                    for (int m = 0; m < 4; m++) {
                        int j = idx + m;
                        if (j < n) {
                            int q = d_qbuf[j];
                            out[j] = (q >= keepv) ? (float)q : 0.0f;
                        }
                    }
                }
            }
        } else {
            // -------- straddling segment (exactly one): ballot ranking -----
            int wcnt = 0;
            for (int rr = 0; rr < SEG / 8 / 128; rr++) {
                int idx = warpbase + rr * 128 + lane * 4;
                uchar4 q = make_uchar4(255, 255, 255, 255);
                unsigned int m = 0;
                if (idx + 3 < n) {
                    q = *reinterpret_cast<const uchar4*>(d_qbuf + idx);
                    m = 0xFu;
                } else {
                    if (idx + 0 < n) { q.x = d_qbuf[idx + 0]; m |= 1u; }
                    if (idx + 1 < n) { q.y = d_qbuf[idx + 1]; m |= 2u; }
                    if (idx + 2 < n) { q.z = d_qbuf[idx + 2]; m |= 4u; }
                }
                unsigned int b0 = __ballot_sync(0xFFFFFFFFu, (m & 1u) && q.x == t);
                unsigned int b1 = __ballot_sync(0xFFFFFFFFu, (m & 2u) && q.y == t);
                unsigned int b2 = __ballot_sync(0xFFFFFFFFu, (m & 4u) && q.z == t);
                unsigned int b3 = __ballot_sync(0xFFFFFFFFu, (m & 8u) && q.w == t);
                wcnt += __popc(b0) + __popc(b1) + __popc(b2) + __popc(b3);
            }
            if (lane == 0) s_wtot[wid] = wcnt;
            __syncthreads();

            int wbase = s;
#pragma unroll
            for (int w = 0; w < 8; w++)
                if (w < wid) wbase += s_wtot[w];

            int run = 0;
            for (int rr = 0; rr < SEG / 8 / 128; rr++) {
                int idx = warpbase + rr * 128 + lane * 4;
                uchar4 q = make_uchar4(255, 255, 255, 255);
                unsigned int m = 0;
                if (idx + 3 < n) {
                    q = *reinterpret_cast<const uchar4*>(d_qbuf + idx);
                    m = 0xFu;
                } else {
                    if (idx + 0 < n) { q.x = d_qbuf[idx + 0]; m |= 1u; }
                    if (idx + 1 < n) { q.y = d_qbuf[idx + 1]; m |= 2u; }
                    if (idx + 2 < n) { q.z = d_qbuf[idx + 2]; m |= 4u; }
                }
                bool t0 = (m & 1u) && q.x == t;
                bool t1 = (m & 2u) && q.y == t;
                bool t2 = (m & 4u) && q.z == t;
                bool t3 = (m & 8u) && q.w == t;
                unsigned int b0 = __ballot_sync(0xFFFFFFFFu, t0);
                unsigned int b1 = __ballot_sync(0xFFFFFFFFu, t1);
                unsigned int b2 = __ballot_sync(0xFFFFFFFFu, t2);
                unsigned int b3 = __ballot_sync(0xFFFFFFFFu, t3);
                int before = __popc(b0 & ltmask) + __popc(b1 & ltmask) +
                             __popc(b2 & ltmask) + __popc(b3 & ltmask);
                int rank = wbase + run + before;
                run += __popc(b0) + __popc(b1) + __popc(b2) + __popc(b3);

                if (m == 0) continue;

                float o0, o1, o2, o3;
                if (q.x > t) o0 = (float)q.x; else if (t0) { o0 = (rank < r) ? (float)q.x : 0.0f; rank++; } else o0 = 0.0f;
                if (q.y > t) o1 = (float)q.y; else if (t1) { o1 = (rank < r) ? (float)q.y : 0.0f; rank++; } else o1 = 0.0f;
                if (q.z > t) o2 = (float)q.z; else if (t2) { o2 = (rank < r) ? (float)q.z : 0.0f; rank++; } else o2 = 0.0f;
                if (q.w > t) o3 = (float)q.w; else if (t3) { o3 = (rank < r) ? (float)q.w : 0.0f; rank++; } else o3 = 0.0f;

                if (m == 0xFu) {
                    float4 ov; ov.x = o0; ov.y = o1; ov.z = o2; ov.w = o3;
                    *reinterpret_cast<float4*>(out + idx) = ov;
                } else {
                    if (m & 1u) out[idx + 0] = o0;
                    if (m & 2u) out[idx + 1] = o1;
                    if (m & 4u) out[idx + 2] = o2;
                }
            }
        }
        __syncthreads();   // red/s_s reused next seg
    }

    if (b == 0 && tid == 0 && out_n >= (long long)n + 3) {
        out[n + 0] = minv;
        out[n + 1] = maxv;
        out[n + 2] = range;
    }
}

// ---------------- launch ----------------
extern "C" void kernel_launch(void* const* d_in, const int* in_sizes, int n_in,
                              void* d_out, int out_size) {
    const float* x = (const float*)d_in[0];
    float* out = (float*)d_out;
    int n = in_sizes[0];
    int nseg = (n + SEG - 1) / SEG;          // 512 for 2^24
    int keep = (int)((double)n * 0.5);       // int(total * (1 - SPARSE_RATIO))

    k_fused<<<NBLK, THREADS>>>(x, out, n, keep, nseg, (long long)out_size);
}

// round 7
// speedup vs baseline: 1.5060x; 1.5060x over previous
#include <cuda_runtime.h>
#include <math_constants.h>

#define THREADS 256
#define SEG 8192              // elements per block in quant/output passes
#define MAXB 4096
#define NELEM_MAX (1 << 24)   // 1*32*4096*128 = 2^24

// ---------------- device scratch (no allocations allowed) ----------------
__device__ unsigned int d_umin = 0xFFFFFFFFu;   // re-armed by tail block
__device__ unsigned int d_umax = 0u;
__device__ int d_hist[256];                     // zeroed by tail block
__device__ int d_bhT[256][MAXB];                // bin-major per-block histogram
__device__ unsigned char d_qbuf[NELEM_MAX];
__device__ int d_t, d_r;
__device__ int d_tieoff[MAXB + 1];              // [b]=excl prefix, [nb]=total
__device__ float d_stats[3];                    // min, max, range
__device__ unsigned int d_done = 0;             // quanthist completion counter

// order-preserving float <-> uint mapping for atomic min/max
__device__ __forceinline__ unsigned int enc_f(float f) {
    unsigned int u = __float_as_uint(f);
    return (u & 0x80000000u) ? ~u : (u | 0x80000000u);
}
__device__ __forceinline__ float dec_f(unsigned int e) {
    unsigned int u = (e & 0x80000000u) ? (e & 0x7FFFFFFFu) : ~e;
    return __uint_as_float(u);
}

// exact quantization matching jnp: ((x-min)/range)*255, round-half-even
__device__ __forceinline__ int quant(float v, float minv, float range) {
    float n = __fdiv_rn(v - minv, range);       // IEEE divide (no fast-math)
    float s = __fmul_rn(n, 255.0f);             // IEEE multiply
    int q = (int)rintf(s);                      // RNE, same as jnp.round
    return min(255, max(0, q));
}

// ---------------- pass 1: global min/max ----------------
__global__ void k_minmax(const float* __restrict__ x, int n) {
    float lmin = CUDART_INF_F, lmax = -CUDART_INF_F;
    int n4 = n >> 2;
    const float4* x4 = reinterpret_cast<const float4*>(x);
    for (int i = blockIdx.x * blockDim.x + threadIdx.x; i < n4;
         i += gridDim.x * blockDim.x) {
        float4 v = x4[i];
        lmin = fminf(lmin, fminf(fminf(v.x, v.y), fminf(v.z, v.w)));
        lmax = fmaxf(lmax, fmaxf(fmaxf(v.x, v.y), fmaxf(v.z, v.w)));
    }
    if (blockIdx.x == 0) {  // scalar tail
        for (int i = n4 * 4 + threadIdx.x; i < n; i += blockDim.x) {
            float v = x[i];
            lmin = fminf(lmin, v);
            lmax = fmaxf(lmax, v);
        }
    }
#pragma unroll
    for (int o = 16; o; o >>= 1) {
        lmin = fminf(lmin, __shfl_xor_sync(0xFFFFFFFFu, lmin, o));
        lmax = fmaxf(lmax, __shfl_xor_sync(0xFFFFFFFFu, lmax, o));
    }
    __shared__ float smin[8], smax[8];
    int lane = threadIdx.x & 31, wid = threadIdx.x >> 5;
    if (lane == 0) { smin[wid] = lmin; smax[wid] = lmax; }
    __syncthreads();
    if (threadIdx.x == 0) {
#pragma unroll
        for (int w = 1; w < 8; w++) {
            lmin = fminf(lmin, smin[w]);
            lmax = fmaxf(lmax, smax[w]);
        }
        atomicMin(&d_umin, enc_f(lmin));
        atomicMax(&d_umax, enc_f(lmax));
    }
}

// ---------------- pass 2: quantize + histogram + tail-block select --------
__global__ void k_quanthist(const float* __restrict__ x, int n, int nb, int keep) {
    __shared__ int sh[8][256];   // per-warp sub-histograms (8 KB)
    __shared__ unsigned int s_isLast;
    __shared__ int s_t;
    __shared__ int red[8];
    int tid = threadIdx.x;
    int lane = tid & 31, wid = tid >> 5;
#pragma unroll
    for (int i = tid; i < 8 * 256; i += THREADS) ((int*)sh)[i] = 0;
    __syncthreads();

    float minv = dec_f(d_umin), maxv = dec_f(d_umax);
    float range = maxv - minv;
    if (range == 0.0f) range = 1.0f;

    int base = blockIdx.x * SEG;
#pragma unroll
    for (int k = 0; k < SEG; k += THREADS * 4) {
        int idx = base + k + tid * 4;
        if (idx + 3 < n) {
            float4 v = __ldcs(reinterpret_cast<const float4*>(x + idx)); // last use
            int q0 = quant(v.x, minv, range);
            int q1 = quant(v.y, minv, range);
            int q2 = quant(v.z, minv, range);
            int q3 = quant(v.w, minv, range);
            atomicAdd(&sh[wid][q0], 1);
            atomicAdd(&sh[wid][q1], 1);
            atomicAdd(&sh[wid][q2], 1);
            atomicAdd(&sh[wid][q3], 1);
            uchar4 qc;
            qc.x = (unsigned char)q0; qc.y = (unsigned char)q1;
            qc.z = (unsigned char)q2; qc.w = (unsigned char)q3;
            *reinterpret_cast<uchar4*>(d_qbuf + idx) = qc;
        } else {
            for (int m = 0; m < 4; m++) {
                int j = idx + m;
                if (j < n) {
                    int q = quant(x[j], minv, range);
                    atomicAdd(&sh[wid][q], 1);
                    d_qbuf[j] = (unsigned char)q;
                }
            }
        }
    }
    __syncthreads();
    int tot = 0;
#pragma unroll
    for (int w = 0; w < 8; w++) tot += sh[w][tid];
    atomicAdd(&d_hist[tid], tot);
    d_bhT[tid][blockIdx.x] = tot;     // bin-major: column t is contiguous

    // ---- tail-block detection ----
    __threadfence();
    __syncthreads();
    if (tid == 0) {
        unsigned int prev = atomicAdd(&d_done, 1u);
        s_isLast = (prev == (unsigned int)(gridDim.x - 1)) ? 1u : 0u;
    }
    __syncthreads();
    if (!s_isLast) return;

    // ================= tail block: selection =================
    // phase A: suffix scan over 256 bins -> (t, r)
    int* sc = &sh[0][0];
    int h = d_hist[tid];
    sc[tid] = h;
    __syncthreads();
#pragma unroll
    for (int off = 1; off < 256; off <<= 1) {
        int add = (tid + off < 256) ? sc[tid + off] : 0;
        __syncthreads();
        sc[tid] += add;
        __syncthreads();
    }
    {
        int ge = sc[tid];
        int gt = ge - h;
        if (gt < keep && ge >= keep) {   // exactly one bin satisfies this
            d_t = tid;
            d_r = keep - gt;
            s_t = tid;
        }
        d_hist[tid] = 0;                 // re-arm
    }
    __syncthreads();
    int t = s_t;

    // phase B: exclusive prefix scan of d_bhT[t][0..nb) (contiguous, L2-hot)
    const int* col = d_bhT[t];
    int per = (nb + THREADS - 1) / THREADS;
    int lo = tid * per;
    int mysum = 0;
    for (int k = 0; k < per; k++) {
        int j = lo + k;
        if (j < nb) mysum += col[j];
    }
    // block exclusive scan of mysum
    int xs = mysum;
#pragma unroll
    for (int o = 1; o < 32; o <<= 1) {
        int y = __shfl_up_sync(0xFFFFFFFFu, xs, o);
        if (lane >= o) xs += y;
    }
    if (lane == 31) red[wid] = xs;
    __syncthreads();
    if (tid < 8) {
        int w = red[tid];
#pragma unroll
        for (int o = 1; o < 8; o <<= 1) {
            int y = __shfl_up_sync(0xFFu, w, o);
            if (tid >= o) w += y;
        }
        red[tid] = w;
    }
    __syncthreads();
    int runp = (xs - mysum) + (wid ? red[wid - 1] : 0);
    for (int k = 0; k < per; k++) {
        int j = lo + k;
        if (j < nb) { d_tieoff[j] = runp; runp += col[j]; }
    }
    if (tid == THREADS - 1) d_tieoff[nb] = runp;

    // re-arm + stats snapshot
    if (tid == 0) {
        d_stats[0] = minv;
        d_stats[1] = maxv;
        d_stats[2] = range;
        d_umin = 0xFFFFFFFFu;
        d_umax = 0u;
        d_done = 0;
    }
}

// ---------------- pass 3: write sparsified output ----------------
// A block keeps ALL its ties (e<=r), NONE (s>=r), or is the single
// straddling block needing intra-block ranking.
__global__ void k_output(float* __restrict__ out, int n, long long out_n) {
    int tid = threadIdx.x;
    int lane = tid & 31, wid = tid >> 5;
    int t = d_t, r = d_r;
    int b = blockIdx.x;
    int s = d_tieoff[b], e = d_tieoff[b + 1];

    int warpbase = b * SEG + wid * 1024;

    if (e <= r || s >= r) {
        // ---- fast path: keep q >= keepv ----
        int keepv = (e <= r) ? t : (t + 1);
#pragma unroll
        for (int rr = 0; rr < 8; rr++) {
            int idx = warpbase + rr * 128 + lane * 4;
            if (idx + 3 < n) {
                uchar4 q = *reinterpret_cast<const uchar4*>(d_qbuf + idx);
                float4 ov;
                ov.x = (q.x >= keepv) ? (float)q.x : 0.0f;
                ov.y = (q.y >= keepv) ? (float)q.y : 0.0f;
                ov.z = (q.z >= keepv) ? (float)q.z : 0.0f;
                ov.w = (q.w >= keepv) ? (float)q.w : 0.0f;
                __stcs(reinterpret_cast<float4*>(out + idx), ov);
            } else {
                for (int m = 0; m < 4; m++) {
                    int j = idx + m;
                    if (j < n) {
                        int q = d_qbuf[j];
                        out[j] = (q >= keepv) ? (float)q : 0.0f;
                    }
                }
            }
        }
    } else {
        // ---- partial path: exactly one block — two-phase ballot ranking ----
        __shared__ int s_wtot[8];
        unsigned int ltmask = (1u << lane) - 1u;

        int wcnt = 0;
#pragma unroll
        for (int rr = 0; rr < 8; rr++) {
            int idx = warpbase + rr * 128 + lane * 4;
            uchar4 q = make_uchar4(255, 255, 255, 255);
            unsigned int m = 0;
            if (idx + 3 < n) {
                q = *reinterpret_cast<const uchar4*>(d_qbuf + idx);
                m = 0xFu;
            } else {
                if (idx + 0 < n) { q.x = d_qbuf[idx + 0]; m |= 1u; }
                if (idx + 1 < n) { q.y = d_qbuf[idx + 1]; m |= 2u; }
                if (idx + 2 < n) { q.z = d_qbuf[idx + 2]; m |= 4u; }
            }
            unsigned int b0 = __ballot_sync(0xFFFFFFFFu, (m & 1u) && q.x == t);
            unsigned int b1 = __ballot_sync(0xFFFFFFFFu, (m & 2u) && q.y == t);
            unsigned int b2 = __ballot_sync(0xFFFFFFFFu, (m & 4u) && q.z == t);
            unsigned int b3 = __ballot_sync(0xFFFFFFFFu, (m & 8u) && q.w == t);
            wcnt += __popc(b0) + __popc(b1) + __popc(b2) + __popc(b3);
        }
        if (lane == 0) s_wtot[wid] = wcnt;
        __syncthreads();

        int wbase = s;
#pragma unroll
        for (int w = 0; w < 8; w++)
            if (w < wid) wbase += s_wtot[w];

        int run = 0;
#pragma unroll
        for (int rr = 0; rr < 8; rr++) {
            int idx = warpbase + rr * 128 + lane * 4;
            uchar4 q = make_uchar4(255, 255, 255, 255);
            unsigned int m = 0;
            if (idx + 3 < n) {
                q = *reinterpret_cast<const uchar4*>(d_qbuf + idx);
                m = 0xFu;
            } else {
                if (idx + 0 < n) { q.x = d_qbuf[idx + 0]; m |= 1u; }
                if (idx + 1 < n) { q.y = d_qbuf[idx + 1]; m |= 2u; }
                if (idx + 2 < n) { q.z = d_qbuf[idx + 2]; m |= 4u; }
            }
            bool t0 = (m & 1u) && q.x == t;
            bool t1 = (m & 2u) && q.y == t;
            bool t2 = (m & 4u) && q.z == t;
            bool t3 = (m & 8u) && q.w == t;
            unsigned int b0 = __ballot_sync(0xFFFFFFFFu, t0);
            unsigned int b1 = __ballot_sync(0xFFFFFFFFu, t1);
            unsigned int b2 = __ballot_sync(0xFFFFFFFFu, t2);
            unsigned int b3 = __ballot_sync(0xFFFFFFFFu, t3);
            int before = __popc(b0 & ltmask) + __popc(b1 & ltmask) +
                         __popc(b2 & ltmask) + __popc(b3 & ltmask);
            int rank = wbase + run + before;
            run += __popc(b0) + __popc(b1) + __popc(b2) + __popc(b3);

            if (m == 0) continue;

            float o0, o1, o2, o3;
            if (q.x > t) o0 = (float)q.x; else if (t0) { o0 = (rank < r) ? (float)q.x : 0.0f; rank++; } else o0 = 0.0f;
            if (q.y > t) o1 = (float)q.y; else if (t1) { o1 = (rank < r) ? (float)q.y : 0.0f; rank++; } else o1 = 0.0f;
            if (q.z > t) o2 = (float)q.z; else if (t2) { o2 = (rank < r) ? (float)q.z : 0.0f; rank++; } else o2 = 0.0f;
            if (q.w > t) o3 = (float)q.w; else if (t3) { o3 = (rank < r) ? (float)q.w : 0.0f; rank++; } else o3 = 0.0f;

            if (m == 0xFu) {
                float4 ov; ov.x = o0; ov.y = o1; ov.z = o2; ov.w = o3;
                __stcs(reinterpret_cast<float4*>(out + idx), ov);
            } else {
                if (m & 1u) out[idx + 0] = o0;
                if (m & 2u) out[idx + 1] = o1;
                if (m & 4u) out[idx + 2] = o2;
            }
        }
    }

    if (b == 0 && tid == 0 && out_n >= (long long)n + 3) {
        out[n + 0] = d_stats[0];
        out[n + 1] = d_stats[1];
        out[n + 2] = d_stats[2];
    }
}

// ---------------- launch ----------------
extern "C" void kernel_launch(void* const* d_in, const int* in_sizes, int n_in,
                              void* d_out, int out_size) {
    const float* x = (const float*)d_in[0];
    float* out = (float*)d_out;
    int n = in_sizes[0];
    int nb = (n + SEG - 1) / SEG;            // 2048 for 2^24
    int keep = (int)((double)n * 0.5);       // int(total * (1 - SPARSE_RATIO))

    k_minmax<<<2048, THREADS>>>(x, n);
    k_quanthist<<<nb, THREADS>>>(x, n, nb, keep);
    k_output<<<nb, THREADS>>>(out, n, (long long)out_size);
}

// round 8
// speedup vs baseline: 1.5182x; 1.0081x over previous
#include <cuda_runtime.h>
#include <math_constants.h>

#define THREADS 256
#define SEG 8192              // elements per block in all streaming passes
#define MAXB 4096
#define NELEM_MAX (1 << 24)   // 1*32*4096*128 = 2^24

// ---------------- device scratch (no allocations allowed) ----------------
__device__ unsigned int d_umin = 0xFFFFFFFFu;   // re-armed by tail block
__device__ unsigned int d_umax = 0u;
__device__ int d_hist[256];                     // zeroed by tail block
__device__ int d_bhT[256][MAXB];                // bin-major per-block histogram
__device__ unsigned char d_qbuf[NELEM_MAX];
__device__ int d_t, d_r;
__device__ int d_tieoff[MAXB + 1];              // [b]=excl prefix, [nb]=total
__device__ float d_stats[3];                    // min, max, range
__device__ unsigned int d_done = 0;             // quanthist completion counter

// order-preserving float <-> uint mapping for atomic min/max
__device__ __forceinline__ unsigned int enc_f(float f) {
    unsigned int u = __float_as_uint(f);
    return (u & 0x80000000u) ? ~u : (u | 0x80000000u);
}
__device__ __forceinline__ float dec_f(unsigned int e) {
    unsigned int u = (e & 0x80000000u) ? (e & 0x7FFFFFFFu) : ~e;
    return __uint_as_float(u);
}

// exact quantization matching jnp: ((x-min)/range)*255, round-half-even
__device__ __forceinline__ int quant(float v, float minv, float range) {
    float n = __fdiv_rn(v - minv, range);       // IEEE divide (no fast-math)
    float s = __fmul_rn(n, 255.0f);             // IEEE multiply
    int q = (int)rintf(s);                      // RNE, same as jnp.round
    return min(255, max(0, q));
}

__device__ __forceinline__ void mm4(float4 v, float& mn, float& mx) {
    mn = fminf(mn, fminf(fminf(v.x, v.y), fminf(v.z, v.w)));
    mx = fmaxf(mx, fmaxf(fmaxf(v.x, v.y), fmaxf(v.z, v.w)));
}

// ---------------- pass 1: global min/max (MLP=4) ----------------
__global__ void k_minmax(const float* __restrict__ x, int n) {
    int tid = threadIdx.x;
    int base = blockIdx.x * SEG;
    float mn0 = CUDART_INF_F, mx0 = -CUDART_INF_F;
    float mn1 = CUDART_INF_F, mx1 = -CUDART_INF_F;
    float mn2 = CUDART_INF_F, mx2 = -CUDART_INF_F;
    float mn3 = CUDART_INF_F, mx3 = -CUDART_INF_F;

    if (base + SEG <= n) {
#pragma unroll
        for (int k = 0; k < SEG; k += 4096) {
            int i0 = base + k + tid * 4;
            float4 v0 = *reinterpret_cast<const float4*>(x + i0);
            float4 v1 = *reinterpret_cast<const float4*>(x + i0 + 1024);
            float4 v2 = *reinterpret_cast<const float4*>(x + i0 + 2048);
            float4 v3 = *reinterpret_cast<const float4*>(x + i0 + 3072);
            mm4(v0, mn0, mx0);
            mm4(v1, mn1, mx1);
            mm4(v2, mn2, mx2);
            mm4(v3, mn3, mx3);
        }
    } else {
        for (int i = base + tid; i < n; i += THREADS) {
            float v = x[i];
            mn0 = fminf(mn0, v);
            mx0 = fmaxf(mx0, v);
        }
    }
    float lmin = fminf(fminf(mn0, mn1), fminf(mn2, mn3));
    float lmax = fmaxf(fmaxf(mx0, mx1), fmaxf(mx2, mx3));
#pragma unroll
    for (int o = 16; o; o >>= 1) {
        lmin = fminf(lmin, __shfl_xor_sync(0xFFFFFFFFu, lmin, o));
        lmax = fmaxf(lmax, __shfl_xor_sync(0xFFFFFFFFu, lmax, o));
    }
    __shared__ float smin[8], smax[8];
    int lane = tid & 31, wid = tid >> 5;
    if (lane == 0) { smin[wid] = lmin; smax[wid] = lmax; }
    __syncthreads();
    if (tid == 0) {
#pragma unroll
        for (int w = 1; w < 8; w++) {
            lmin = fminf(lmin, smin[w]);
            lmax = fmaxf(lmax, smax[w]);
        }
        atomicMin(&d_umin, enc_f(lmin));
        atomicMax(&d_umax, enc_f(lmax));
    }
}

// ---------------- pass 2: quantize + histogram + tail-block select --------
__global__ void k_quanthist(const float* __restrict__ x, int n, int nb, int keep) {
    __shared__ int sh[8][256];   // per-warp sub-histograms (8 KB)
    __shared__ unsigned int s_isLast;
    __shared__ int s_t;
    __shared__ int red[8];
    int tid = threadIdx.x;
    int lane = tid & 31, wid = tid >> 5;
#pragma unroll
    for (int i = tid; i < 8 * 256; i += THREADS) ((int*)sh)[i] = 0;
    __syncthreads();

    float minv = dec_f(d_umin), maxv = dec_f(d_umax);
    float range = maxv - minv;
    if (range == 0.0f) range = 1.0f;

    int base = blockIdx.x * SEG;
    if (base + SEG <= n) {
#pragma unroll
        for (int k = 0; k < SEG; k += 4096) {
            int i0 = base + k + tid * 4;
            float4 v0 = __ldcs(reinterpret_cast<const float4*>(x + i0));
            float4 v1 = __ldcs(reinterpret_cast<const float4*>(x + i0 + 1024));
            float4 v2 = __ldcs(reinterpret_cast<const float4*>(x + i0 + 2048));
            float4 v3 = __ldcs(reinterpret_cast<const float4*>(x + i0 + 3072));

            int q00 = quant(v0.x, minv, range), q01 = quant(v0.y, minv, range);
            int q02 = quant(v0.z, minv, range), q03 = quant(v0.w, minv, range);
            int q10 = quant(v1.x, minv, range), q11 = quant(v1.y, minv, range);
            int q12 = quant(v1.z, minv, range), q13 = quant(v1.w, minv, range);
            int q20 = quant(v2.x, minv, range), q21 = quant(v2.y, minv, range);
            int q22 = quant(v2.z, minv, range), q23 = quant(v2.w, minv, range);
            int q30 = quant(v3.x, minv, range), q31 = quant(v3.y, minv, range);
            int q32 = quant(v3.z, minv, range), q33 = quant(v3.w, minv, range);

            atomicAdd(&sh[wid][q00], 1); atomicAdd(&sh[wid][q01], 1);
            atomicAdd(&sh[wid][q02], 1); atomicAdd(&sh[wid][q03], 1);
            atomicAdd(&sh[wid][q10], 1); atomicAdd(&sh[wid][q11], 1);
            atomicAdd(&sh[wid][q12], 1); atomicAdd(&sh[wid][q13], 1);
            atomicAdd(&sh[wid][q20], 1); atomicAdd(&sh[wid][q21], 1);
            atomicAdd(&sh[wid][q22], 1); atomicAdd(&sh[wid][q23], 1);
            atomicAdd(&sh[wid][q30], 1); atomicAdd(&sh[wid][q31], 1);
            atomicAdd(&sh[wid][q32], 1); atomicAdd(&sh[wid][q33], 1);

            *reinterpret_cast<uchar4*>(d_qbuf + i0) =
                make_uchar4((unsigned char)q00, (unsigned char)q01,
                            (unsigned char)q02, (unsigned char)q03);
            *reinterpret_cast<uchar4*>(d_qbuf + i0 + 1024) =
                make_uchar4((unsigned char)q10, (unsigned char)q11,
                            (unsigned char)q12, (unsigned char)q13);
            *reinterpret_cast<uchar4*>(d_qbuf + i0 + 2048) =
                make_uchar4((unsigned char)q20, (unsigned char)q21,
                            (unsigned char)q22, (unsigned char)q23);
            *reinterpret_cast<uchar4*>(d_qbuf + i0 + 3072) =
                make_uchar4((unsigned char)q30, (unsigned char)q31,
                            (unsigned char)q32, (unsigned char)q33);
        }
    } else {
        for (int j = base + tid; j < n; j += THREADS) {
            int q = quant(x[j], minv, range);
            atomicAdd(&sh[wid][q], 1);
            d_qbuf[j] = (unsigned char)q;
        }
    }
    __syncthreads();
    int tot = 0;
#pragma unroll
    for (int w = 0; w < 8; w++) tot += sh[w][tid];
    atomicAdd(&d_hist[tid], tot);
    d_bhT[tid][blockIdx.x] = tot;     // bin-major: column t is contiguous

    // ---- tail-block detection ----
    __threadfence();
    __syncthreads();
    if (tid == 0) {
        unsigned int prev = atomicAdd(&d_done, 1u);
        s_isLast = (prev == (unsigned int)(gridDim.x - 1)) ? 1u : 0u;
    }
    __syncthreads();
    if (!s_isLast) return;

    // ================= tail block: selection =================
    int* sc = &sh[0][0];
    int h = d_hist[tid];
    sc[tid] = h;
    __syncthreads();
#pragma unroll
    for (int off = 1; off < 256; off <<= 1) {
        int add = (tid + off < 256) ? sc[tid + off] : 0;
        __syncthreads();
        sc[tid] += add;
        __syncthreads();
    }
    {
        int ge = sc[tid];
        int gt = ge - h;
        if (gt < keep && ge >= keep) {   // exactly one bin satisfies this
            d_t = tid;
            d_r = keep - gt;
            s_t = tid;
        }
        d_hist[tid] = 0;                 // re-arm
    }
    __syncthreads();
    int t = s_t;

    // exclusive prefix scan of d_bhT[t][0..nb) (contiguous, L2-hot)
    const int* col = d_bhT[t];
    int per = (nb + THREADS - 1) / THREADS;
    int lo = tid * per;
    int mysum = 0;
    for (int k = 0; k < per; k++) {
        int j = lo + k;
        if (j < nb) mysum += col[j];
    }
    int xs = mysum;
#pragma unroll
    for (int o = 1; o < 32; o <<= 1) {
        int y = __shfl_up_sync(0xFFFFFFFFu, xs, o);
        if (lane >= o) xs += y;
    }
    if (lane == 31) red[wid] = xs;
    __syncthreads();
    if (tid < 8) {
        int w = red[tid];
#pragma unroll
        for (int o = 1; o < 8; o <<= 1) {
            int y = __shfl_up_sync(0xFFu, w, o);
            if (tid >= o) w += y;
        }
        red[tid] = w;
    }
    __syncthreads();
    int runp = (xs - mysum) + (wid ? red[wid - 1] : 0);
    for (int k = 0; k < per; k++) {
        int j = lo + k;
        if (j < nb) { d_tieoff[j] = runp; runp += col[j]; }
    }
    if (tid == THREADS - 1) d_tieoff[nb] = runp;

    if (tid == 0) {
        d_stats[0] = minv;
        d_stats[1] = maxv;
        d_stats[2] = range;
        d_umin = 0xFFFFFFFFu;
        d_umax = 0u;
        d_done = 0;
    }
}

// ---------------- pass 3: write sparsified output ----------------
__global__ void k_output(float* __restrict__ out, int n, long long out_n) {
    int tid = threadIdx.x;
    int lane = tid & 31, wid = tid >> 5;
    int t = d_t, r = d_r;
    int b = blockIdx.x;
    int s = d_tieoff[b], e = d_tieoff[b + 1];

    int warpbase = b * SEG + wid * 1024;

    if (e <= r || s >= r) {
        // ---- fast path: keep q >= keepv, front-batched loads (MLP=8) ----
        int keepv = (e <= r) ? t : (t + 1);
        if (b * SEG + SEG <= n) {
            uchar4 qv[8];
#pragma unroll
            for (int rr = 0; rr < 8; rr++)
                qv[rr] = *reinterpret_cast<const uchar4*>(
                    d_qbuf + warpbase + rr * 128 + lane * 4);
#pragma unroll
            for (int rr = 0; rr < 8; rr++) {
                uchar4 q = qv[rr];
                float4 ov;
                ov.x = (q.x >= keepv) ? (float)q.x : 0.0f;
                ov.y = (q.y >= keepv) ? (float)q.y : 0.0f;
                ov.z = (q.z >= keepv) ? (float)q.z : 0.0f;
                ov.w = (q.w >= keepv) ? (float)q.w : 0.0f;
                __stcs(reinterpret_cast<float4*>(out + warpbase + rr * 128 + lane * 4), ov);
            }
        } else {
            for (int rr = 0; rr < 8; rr++) {
                int idx = warpbase + rr * 128 + lane * 4;
                for (int m = 0; m < 4; m++) {
                    int j = idx + m;
                    if (j < n) {
                        int q = d_qbuf[j];
                        out[j] = (q >= keepv) ? (float)q : 0.0f;
                    }
                }
            }
        }
    } else {
        // ---- partial path: exactly one block — two-phase ballot ranking ----
        __shared__ int s_wtot[8];
        unsigned int ltmask = (1u << lane) - 1u;

        int wcnt = 0;
#pragma unroll
        for (int rr = 0; rr < 8; rr++) {
            int idx = warpbase + rr * 128 + lane * 4;
            uchar4 q = make_uchar4(255, 255, 255, 255);
            unsigned int m = 0;
            if (idx + 3 < n) {
                q = *reinterpret_cast<const uchar4*>(d_qbuf + idx);
                m = 0xFu;
            } else {
                if (idx + 0 < n) { q.x = d_qbuf[idx + 0]; m |= 1u; }
                if (idx + 1 < n) { q.y = d_qbuf[idx + 1]; m |= 2u; }
                if (idx + 2 < n) { q.z = d_qbuf[idx + 2]; m |= 4u; }
            }
            unsigned int b0 = __ballot_sync(0xFFFFFFFFu, (m & 1u) && q.x == t);
            unsigned int b1 = __ballot_sync(0xFFFFFFFFu, (m & 2u) && q.y == t);
            unsigned int b2 = __ballot_sync(0xFFFFFFFFu, (m & 4u) && q.z == t);
            unsigned int b3 = __ballot_sync(0xFFFFFFFFu, (m & 8u) && q.w == t);
            wcnt += __popc(b0) + __popc(b1) + __popc(b2) + __popc(b3);
        }
        if (lane == 0) s_wtot[wid] = wcnt;
        __syncthreads();

        int wbase = s;
#pragma unroll
        for (int w = 0; w < 8; w++)
            if (w < wid) wbase += s_wtot[w];

        int run = 0;
#pragma unroll
        for (int rr = 0; rr < 8; rr++) {
            int idx = warpbase + rr * 128 + lane * 4;
            uchar4 q = make_uchar4(255, 255, 255, 255);
            unsigned int m = 0;
            if (idx + 3 < n) {
                q = *reinterpret_cast<const uchar4*>(d_qbuf + idx);
                m = 0xFu;
            } else {
                if (idx + 0 < n) { q.x = d_qbuf[idx + 0]; m |= 1u; }
                if (idx + 1 < n) { q.y = d_qbuf[idx + 1]; m |= 2u; }
                if (idx + 2 < n) { q.z = d_qbuf[idx + 2]; m |= 4u; }
            }
            bool t0 = (m & 1u) && q.x == t;
            bool t1 = (m & 2u) && q.y == t;
            bool t2 = (m & 4u) && q.z == t;
            bool t3 = (m & 8u) && q.w == t;
            unsigned int b0 = __ballot_sync(0xFFFFFFFFu, t0);
            unsigned int b1 = __ballot_sync(0xFFFFFFFFu, t1);
            unsigned int b2 = __ballot_sync(0xFFFFFFFFu, t2);
            unsigned int b3 = __ballot_sync(0xFFFFFFFFu, t3);
            int before = __popc(b0 & ltmask) + __popc(b1 & ltmask) +
                         __popc(b2 & ltmask) + __popc(b3 & ltmask);
            int rank = wbase + run + before;
            run += __popc(b0) + __popc(b1) + __popc(b2) + __popc(b3);

            if (m == 0) continue;

            float o0, o1, o2, o3;
            if (q.x > t) o0 = (float)q.x; else if (t0) { o0 = (rank < r) ? (float)q.x : 0.0f; rank++; } else o0 = 0.0f;
            if (q.y > t) o1 = (float)q.y; else if (t1) { o1 = (rank < r) ? (float)q.y : 0.0f; rank++; } else o1 = 0.0f;
            if (q.z > t) o2 = (float)q.z; else if (t2) { o2 = (rank < r) ? (float)q.z : 0.0f; rank++; } else o2 = 0.0f;
            if (q.w > t) o3 = (float)q.w; else if (t3) { o3 = (rank < r) ? (float)q.w : 0.0f; rank++; } else o3 = 0.0f;

            if (m == 0xFu) {
                float4 ov; ov.x = o0; ov.y = o1; ov.z = o2; ov.w = o3;
                __stcs(reinterpret_cast<float4*>(out + idx), ov);
            } else {
                if (m & 1u) out[idx + 0] = o0;
                if (m & 2u) out[idx + 1] = o1;
                if (m & 4u) out[idx + 2] = o2;
            }
        }
    }

    if (b == 0 && tid == 0 && out_n >= (long long)n + 3) {
        out[n + 0] = d_stats[0];
        out[n + 1] = d_stats[1];
        out[n + 2] = d_stats[2];
    }
}

// ---------------- launch ----------------
extern "C" void kernel_launch(void* const* d_in, const int* in_sizes, int n_in,
                              void* d_out, int out_size) {
    const float* x = (const float*)d_in[0];
    float* out = (float*)d_out;
    int n = in_sizes[0];
    int nb = (n + SEG - 1) / SEG;            // 2048 for 2^24
    int keep = (int)((double)n * 0.5);       // int(total * (1 - SPARSE_RATIO))

    k_minmax<<<nb, THREADS>>>(x, n);
    k_quanthist<<<nb, THREADS>>>(x, n, nb, keep);
    k_output<<<nb, THREADS>>>(out, n, (long long)out_size);
}

// round 9
// speedup vs baseline: 1.5478x; 1.0195x over previous
#include <cuda_runtime.h>
#include <math_constants.h>

#define THREADS 256
#define SEG 8192              // elements per block in all streaming passes
#define MAXB 4096
#define NELEM_MAX (1 << 24)   // 1*32*4096*128 = 2^24

// ---------------- device scratch (no allocations allowed) ----------------
__device__ unsigned int d_umin = 0xFFFFFFFFu;   // re-armed by tail block
__device__ unsigned int d_umax = 0u;
__device__ int d_hist[256];                     // zeroed by tail block
__device__ int d_bhT[256][MAXB];                // bin-major per-block histogram
__device__ unsigned char d_qbuf[NELEM_MAX];
__device__ int d_t, d_r;
__device__ int d_tieoff[MAXB + 1];              // [b]=excl prefix, [nb]=total
__device__ float d_stats[3];                    // min, max, range
__device__ unsigned int d_done = 0;             // quanthist completion counter

// order-preserving float <-> uint mapping for atomic min/max
__device__ __forceinline__ unsigned int enc_f(float f) {
    unsigned int u = __float_as_uint(f);
    return (u & 0x80000000u) ? ~u : (u | 0x80000000u);
}
__device__ __forceinline__ float dec_f(unsigned int e) {
    unsigned int u = (e & 0x80000000u) ? (e & 0x7FFFFFFFu) : ~e;
    return __uint_as_float(u);
}

// exact quantization matching jnp: ((x-min)/range)*255, round-half-even
__device__ __forceinline__ int quant(float v, float minv, float range) {
    float n = __fdiv_rn(v - minv, range);       // IEEE divide (no fast-math)
    float s = __fmul_rn(n, 255.0f);             // IEEE multiply
    int q = (int)rintf(s);                      // RNE, same as jnp.round
    return min(255, max(0, q));
}

__device__ __forceinline__ void mm4(float4 v, float& mn, float& mx) {
    mn = fminf(mn, fminf(fminf(v.x, v.y), fminf(v.z, v.w)));
    mx = fmaxf(mx, fmaxf(fmaxf(v.x, v.y), fmaxf(v.z, v.w)));
}

// ---------------- pass 1: global min/max (MLP=8, one round) ----------------
__global__ void k_minmax(const float* __restrict__ x, int n) {
    int tid = threadIdx.x;
    int base = blockIdx.x * SEG;
    float mn = CUDART_INF_F, mx = -CUDART_INF_F;

    if (base + SEG <= n) {
        float4 v[8];
#pragma unroll
        for (int j = 0; j < 8; j++)
            v[j] = *reinterpret_cast<const float4*>(x + base + j * 1024 + tid * 4);
        float mn0 = CUDART_INF_F, mx0 = -CUDART_INF_F;
        float mn1 = CUDART_INF_F, mx1 = -CUDART_INF_F;
#pragma unroll
        for (int j = 0; j < 8; j += 2) {
            mm4(v[j],     mn0, mx0);
            mm4(v[j + 1], mn1, mx1);
        }
        mn = fminf(mn0, mn1);
        mx = fmaxf(mx0, mx1);
    } else {
        for (int i = base + tid; i < n; i += THREADS) {
            float vv = x[i];
            mn = fminf(mn, vv);
            mx = fmaxf(mx, vv);
        }
    }
#pragma unroll
    for (int o = 16; o; o >>= 1) {
        mn = fminf(mn, __shfl_xor_sync(0xFFFFFFFFu, mn, o));
        mx = fmaxf(mx, __shfl_xor_sync(0xFFFFFFFFu, mx, o));
    }
    __shared__ float smin[8], smax[8];
    int lane = tid & 31, wid = tid >> 5;
    if (lane == 0) { smin[wid] = mn; smax[wid] = mx; }
    __syncthreads();
    if (tid == 0) {
#pragma unroll
        for (int w = 1; w < 8; w++) {
            mn = fminf(mn, smin[w]);
            mx = fmaxf(mx, smax[w]);
        }
        atomicMin(&d_umin, enc_f(mn));
        atomicMax(&d_umax, enc_f(mx));
    }
}

// ---------------- pass 2: quantize + histogram + tail-block select --------
__global__ void k_quanthist(const float* __restrict__ x, int n, int nb, int keep) {
    __shared__ int sh[8][256];   // per-warp sub-histograms (8 KB)
    __shared__ unsigned int s_isLast;
    __shared__ int s_t;
    __shared__ int red[8];
    int tid = threadIdx.x;
    int lane = tid & 31, wid = tid >> 5;
#pragma unroll
    for (int i = tid; i < 8 * 256; i += THREADS) ((int*)sh)[i] = 0;
    __syncthreads();

    // wait for k_minmax grid to complete (PDL) — prologue above overlapped
    cudaGridDependencySynchronize();

    float minv = dec_f(d_umin), maxv = dec_f(d_umax);
    float range = maxv - minv;
    if (range == 0.0f) range = 1.0f;

    int base = blockIdx.x * SEG;
    if (base + SEG <= n) {
#pragma unroll
        for (int k = 0; k < SEG; k += 4096) {
            int i0 = base + k + tid * 4;
            float4 v0 = __ldcs(reinterpret_cast<const float4*>(x + i0));
            float4 v1 = __ldcs(reinterpret_cast<const float4*>(x + i0 + 1024));
            float4 v2 = __ldcs(reinterpret_cast<const float4*>(x + i0 + 2048));
            float4 v3 = __ldcs(reinterpret_cast<const float4*>(x + i0 + 3072));

            int q00 = quant(v0.x, minv, range), q01 = quant(v0.y, minv, range);
            int q02 = quant(v0.z, minv, range), q03 = quant(v0.w, minv, range);
            int q10 = quant(v1.x, minv, range), q11 = quant(v1.y, minv, range);
            int q12 = quant(v1.z, minv, range), q13 = quant(v1.w, minv, range);
            int q20 = quant(v2.x, minv, range), q21 = quant(v2.y, minv, range);
            int q22 = quant(v2.z, minv, range), q23 = quant(v2.w, minv, range);
            int q30 = quant(v3.x, minv, range), q31 = quant(v3.y, minv, range);
            int q32 = quant(v3.z, minv, range), q33 = quant(v3.w, minv, range);

            atomicAdd(&sh[wid][q00], 1); atomicAdd(&sh[wid][q01], 1);
            atomicAdd(&sh[wid][q02], 1); atomicAdd(&sh[wid][q03], 1);
            atomicAdd(&sh[wid][q10], 1); atomicAdd(&sh[wid][q11], 1);
            atomicAdd(&sh[wid][q12], 1); atomicAdd(&sh[wid][q13], 1);
            atomicAdd(&sh[wid][q20], 1); atomicAdd(&sh[wid][q21], 1);
            atomicAdd(&sh[wid][q22], 1); atomicAdd(&sh[wid][q23], 1);
            atomicAdd(&sh[wid][q30], 1); atomicAdd(&sh[wid][q31], 1);
            atomicAdd(&sh[wid][q32], 1); atomicAdd(&sh[wid][q33], 1);

            *reinterpret_cast<uchar4*>(d_qbuf + i0) =
                make_uchar4((unsigned char)q00, (unsigned char)q01,
                            (unsigned char)q02, (unsigned char)q03);
            *reinterpret_cast<uchar4*>(d_qbuf + i0 + 1024) =
                make_uchar4((unsigned char)q10, (unsigned char)q11,
                            (unsigned char)q12, (unsigned char)q13);
            *reinterpret_cast<uchar4*>(d_qbuf + i0 + 2048) =
                make_uchar4((unsigned char)q20, (unsigned char)q21,
                            (unsigned char)q22, (unsigned char)q23);
            *reinterpret_cast<uchar4*>(d_qbuf + i0 + 3072) =
                make_uchar4((unsigned char)q30, (unsigned char)q31,
                            (unsigned char)q32, (unsigned char)q33);
        }
    } else {
        for (int j = base + tid; j < n; j += THREADS) {
            int q = quant(x[j], minv, range);
            atomicAdd(&sh[wid][q], 1);
            d_qbuf[j] = (unsigned char)q;
        }
    }
    __syncthreads();
    int tot = 0;
#pragma unroll
    for (int w = 0; w < 8; w++) tot += sh[w][tid];
    atomicAdd(&d_hist[tid], tot);
    d_bhT[tid][blockIdx.x] = tot;     // bin-major: column t is contiguous

    // ---- tail-block detection ----
    __threadfence();
    __syncthreads();
    if (tid == 0) {
        unsigned int prev = atomicAdd(&d_done, 1u);
        s_isLast = (prev == (unsigned int)(gridDim.x - 1)) ? 1u : 0u;
    }
    __syncthreads();
    if (!s_isLast) return;

    // ================= tail block: selection =================
    int* sc = &sh[0][0];
    int h = d_hist[tid];
    sc[tid] = h;
    __syncthreads();
#pragma unroll
    for (int off = 1; off < 256; off <<= 1) {
        int add = (tid + off < 256) ? sc[tid + off] : 0;
        __syncthreads();
        sc[tid] += add;
        __syncthreads();
    }
    {
        int ge = sc[tid];
        int gt = ge - h;
        if (gt < keep && ge >= keep) {   // exactly one bin satisfies this
            d_t = tid;
            d_r = keep - gt;
            s_t = tid;
        }
        d_hist[tid] = 0;                 // re-arm
    }
    __syncthreads();
    int t = s_t;

    // exclusive prefix scan of d_bhT[t][0..nb) (contiguous, L2-hot)
    const int* col = d_bhT[t];
    int per = (nb + THREADS - 1) / THREADS;
    int lo = tid * per;
    int mysum = 0;
    for (int k = 0; k < per; k++) {
        int j = lo + k;
        if (j < nb) mysum += col[j];
    }
    int xs = mysum;
#pragma unroll
    for (int o = 1; o < 32; o <<= 1) {
        int y = __shfl_up_sync(0xFFFFFFFFu, xs, o);
        if (lane >= o) xs += y;
    }
    if (lane == 31) red[wid] = xs;
    __syncthreads();
    if (tid < 8) {
        int w = red[tid];
#pragma unroll
        for (int o = 1; o < 8; o <<= 1) {
            int y = __shfl_up_sync(0xFFu, w, o);
            if (tid >= o) w += y;
        }
        red[tid] = w;
    }
    __syncthreads();
    int runp = (xs - mysum) + (wid ? red[wid - 1] : 0);
    for (int k = 0; k < per; k++) {
        int j = lo + k;
        if (j < nb) { d_tieoff[j] = runp; runp += col[j]; }
    }
    if (tid == THREADS - 1) d_tieoff[nb] = runp;

    if (tid == 0) {
        d_stats[0] = minv;
        d_stats[1] = maxv;
        d_stats[2] = range;
        d_umin = 0xFFFFFFFFu;
        d_umax = 0u;
        d_done = 0;
    }
}

// ---------------- pass 3: write sparsified output ----------------
__global__ void k_output(float* __restrict__ out, int n, long long out_n) {
    int tid = threadIdx.x;
    int lane = tid & 31, wid = tid >> 5;
    int b = blockIdx.x;
    int warpbase = b * SEG + wid * 1024;

    // wait for k_quanthist grid (incl. tail-block selection) — PDL
    cudaGridDependencySynchronize();

    int t = d_t, r = d_r;
    int s = d_tieoff[b], e = d_tieoff[b + 1];

    if (e <= r || s >= r) {
        // ---- fast path: keep q >= keepv, front-batched loads (MLP=8) ----
        int keepv = (e <= r) ? t : (t + 1);
        if (b * SEG + SEG <= n) {
            uchar4 qv[8];
#pragma unroll
            for (int rr = 0; rr < 8; rr++)
                qv[rr] = *reinterpret_cast<const uchar4*>(
                    d_qbuf + warpbase + rr * 128 + lane * 4);
#pragma unroll
            for (int rr = 0; rr < 8; rr++) {
                uchar4 q = qv[rr];
                float4 ov;
                ov.x = (q.x >= keepv) ? (float)q.x : 0.0f;
                ov.y = (q.y >= keepv) ? (float)q.y : 0.0f;
                ov.z = (q.z >= keepv) ? (float)q.z : 0.0f;
                ov.w = (q.w >= keepv) ? (float)q.w : 0.0f;
                __stcs(reinterpret_cast<float4*>(out + warpbase + rr * 128 + lane * 4), ov);
            }
        } else {
            for (int rr = 0; rr < 8; rr++) {
                int idx = warpbase + rr * 128 + lane * 4;
                for (int m = 0; m < 4; m++) {
                    int j = idx + m;
                    if (j < n) {
                        int q = d_qbuf[j];
                        out[j] = (q >= keepv) ? (float)q : 0.0f;
                    }
                }
            }
        }
    } else {
        // ---- partial path: exactly one block — two-phase ballot ranking ----
        __shared__ int s_wtot[8];
        unsigned int ltmask = (1u << lane) - 1u;

        int wcnt = 0;
#pragma unroll
        for (int rr = 0; rr < 8; rr++) {
            int idx = warpbase + rr * 128 + lane * 4;
            uchar4 q = make_uchar4(255, 255, 255, 255);
            unsigned int m = 0;
            if (idx + 3 < n) {
                q = *reinterpret_cast<const uchar4*>(d_qbuf + idx);
                m = 0xFu;
            } else {
                if (idx + 0 < n) { q.x = d_qbuf[idx + 0]; m |= 1u; }
                if (idx + 1 < n) { q.y = d_qbuf[idx + 1]; m |= 2u; }
                if (idx + 2 < n) { q.z = d_qbuf[idx + 2]; m |= 4u; }
            }
            unsigned int b0 = __ballot_sync(0xFFFFFFFFu, (m & 1u) && q.x == t);
            unsigned int b1 = __ballot_sync(0xFFFFFFFFu, (m & 2u) && q.y == t);
            unsigned int b2 = __ballot_sync(0xFFFFFFFFu, (m & 4u) && q.z == t);
            unsigned int b3 = __ballot_sync(0xFFFFFFFFu, (m & 8u) && q.w == t);
            wcnt += __popc(b0) + __popc(b1) + __popc(b2) + __popc(b3);
        }
        if (lane == 0) s_wtot[wid] = wcnt;
        __syncthreads();

        int wbase = s;
#pragma unroll
        for (int w = 0; w < 8; w++)
            if (w < wid) wbase += s_wtot[w];

        int run = 0;
#pragma unroll
        for (int rr = 0; rr < 8; rr++) {
            int idx = warpbase + rr * 128 + lane * 4;
            uchar4 q = make_uchar4(255, 255, 255, 255);
            unsigned int m = 0;
            if (idx + 3 < n) {
                q = *reinterpret_cast<const uchar4*>(d_qbuf + idx);
                m = 0xFu;
            } else {
                if (idx + 0 < n) { q.x = d_qbuf[idx + 0]; m |= 1u; }
                if (idx + 1 < n) { q.y = d_qbuf[idx + 1]; m |= 2u; }
                if (idx + 2 < n) { q.z = d_qbuf[idx + 2]; m |= 4u; }
            }
            bool t0 = (m & 1u) && q.x == t;
            bool t1 = (m & 2u) && q.y == t;
            bool t2 = (m & 4u) && q.z == t;
            bool t3 = (m & 8u) && q.w == t;
            unsigned int b0 = __ballot_sync(0xFFFFFFFFu, t0);
            unsigned int b1 = __ballot_sync(0xFFFFFFFFu, t1);
            unsigned int b2 = __ballot_sync(0xFFFFFFFFu, t2);
            unsigned int b3 = __ballot_sync(0xFFFFFFFFu, t3);
            int before = __popc(b0 & ltmask) + __popc(b1 & ltmask) +
                         __popc(b2 & ltmask) + __popc(b3 & ltmask);
            int rank = wbase + run + before;
            run += __popc(b0) + __popc(b1) + __popc(b2) + __popc(b3);

            if (m == 0) continue;

            float o0, o1, o2, o3;
            if (q.x > t) o0 = (float)q.x; else if (t0) { o0 = (rank < r) ? (float)q.x : 0.0f; rank++; } else o0 = 0.0f;
            if (q.y > t) o1 = (float)q.y; else if (t1) { o1 = (rank < r) ? (float)q.y : 0.0f; rank++; } else o1 = 0.0f;
            if (q.z > t) o2 = (float)q.z; else if (t2) { o2 = (rank < r) ? (float)q.z : 0.0f; rank++; } else o2 = 0.0f;
            if (q.w > t) o3 = (float)q.w; else if (t3) { o3 = (rank < r) ? (float)q.w : 0.0f; rank++; } else o3 = 0.0f;

            if (m == 0xFu) {
                float4 ov; ov.x = o0; ov.y = o1; ov.z = o2; ov.w = o3;
                __stcs(reinterpret_cast<float4*>(out + idx), ov);
            } else {
                if (m & 1u) out[idx + 0] = o0;
                if (m & 2u) out[idx + 1] = o1;
                if (m & 4u) out[idx + 2] = o2;
            }
        }
    }

    if (b == 0 && tid == 0 && out_n >= (long long)n + 3) {
        out[n + 0] = d_stats[0];
        out[n + 1] = d_stats[1];
        out[n + 2] = d_stats[2];
    }
}

// ---------------- launch ----------------
static void launch_pdl(void* func, dim3 grid, dim3 block, void** args) {
    cudaLaunchConfig_t cfg = {};
    cfg.gridDim = grid;
    cfg.blockDim = block;
    cudaLaunchAttribute attr[1];
    attr[0].id = cudaLaunchAttributeProgrammaticStreamSerialization;
    attr[0].val.programmaticStreamSerializationAllowed = 1;
    cfg.attrs = attr;
    cfg.numAttrs = 1;
    cudaLaunchKernelExC(&cfg, func, args);
}

extern "C" void kernel_launch(void* const* d_in, const int* in_sizes, int n_in,
                              void* d_out, int out_size) {
    const float* x = (const float*)d_in[0];
    float* out = (float*)d_out;
    int n = in_sizes[0];
    int nb = (n + SEG - 1) / SEG;            // 2048 for 2^24
    int keep = (int)((double)n * 0.5);       // int(total * (1 - SPARSE_RATIO))
    long long out_n = (long long)out_size;

    k_minmax<<<nb, THREADS>>>(x, n);

    {   // PDL: overlaps launch+prologue with k_minmax tail
        void* args[] = {(void*)&x, (void*)&n, (void*)&nb, (void*)&keep};
        launch_pdl((void*)k_quanthist, dim3(nb), dim3(THREADS), args);
    }
    {   // PDL: overlaps launch+prologue with k_quanthist tail
        void* args[] = {(void*)&out, (void*)&n, (void*)&out_n};
        launch_pdl((void*)k_output, dim3(nb), dim3(THREADS), args);
    }
}